// round 7
// baseline (speedup 1.0000x reference)
#include <cuda_runtime.h>
#include <cuda_fp16.h>
#include <cstdint>

#define HW    512
#define NPIX  (HW * HW)          // 262144
#define NC    64
#define CAP   16                 // bucket capacity (max Poisson(1) over 262k keys ~ 10)
#define MAXS  40                 // fixed list slots: pass1 [0,9), pass2 [9,40)
#define P2OFF 9
#define NQ2   20                 // int2 words per list row (40 ints)

// Scratch (__device__ globals; zero-initialized at load, row NPIX never written)
__device__ __half g_refT[(size_t)(NPIX + 1) * NC];  // +1 zero row for padded slots
__device__ int    g_cnt[NPIX];                      // bucket counts for inverse nnf_rs
__device__ int    g_bucket[CAP][NPIX];              // interleaved: [slot][key] -> ref pixel r
__device__ int2   g_list[(size_t)NPIX * NQ2];       // pixel-major padded lists: 40 MB
__device__ int    g_counts[NPIX];                   // m1 | (n2 << 16)

// ---------------------------------------------------------------------------
// 1) Transpose + downconvert: ref (C,H,W) fp32 -> refT (H*W, C) fp16.
// ---------------------------------------------------------------------------
__global__ __launch_bounds__(256) void transpose_ref_kernel(const float* __restrict__ ref) {
    __shared__ float tile[64][65];
    const int pixBase = blockIdx.x * 64;
    const int tx = threadIdx.x;   // 0..63
    const int ty = threadIdx.y;   // 0..3

    #pragma unroll
    for (int c = ty; c < NC; c += 4)
        tile[c][tx] = ref[(size_t)c * NPIX + pixBase + tx];   // coalesced over pixels
    __syncthreads();
    #pragma unroll
    for (int p = ty; p < 64; p += 4)
        g_refT[(size_t)(pixBase + p) * NC + tx] = __float2half(tile[tx][p]);
}

// ---------------------------------------------------------------------------
// 2a) Zero bucket counts.  2b) Invert nnf_rs into buckets.
// ---------------------------------------------------------------------------
__global__ __launch_bounds__(256) void zero_cnt_kernel() {
    const int i = blockIdx.x * blockDim.x + threadIdx.x;
    if (i < NPIX) g_cnt[i] = 0;
}
__global__ __launch_bounds__(256) void build_buckets_kernel(const int* __restrict__ nnf_rs) {
    const int r = blockIdx.x * blockDim.x + threadIdx.x;
    if (r >= NPIX) return;
    const int2 nn = ((const int2*)nnf_rs)[r];     // (sy, sx) in [0,512)
    const int key = nn.x * HW + nn.y;
    const int slot = atomicAdd(&g_cnt[key], 1);
    if (slot < CAP) g_bucket[slot][key] = r;
}

// ---------------------------------------------------------------------------
// 3) Precompute padded gather lists, one THREAD per pixel. Unused slots get
//    the zero-row index NPIX. Pass1 -> [0,9), pass2 -> [9, 9+n2).
// ---------------------------------------------------------------------------
__global__ __launch_bounds__(128) void precompute_kernel(const int* __restrict__ nnf_sr) {
    __shared__ int s_list[128][MAXS + 1];         // +1 pad: conflict-free columns
    const int tid = threadIdx.x;
    const int base = blockIdx.x * 128;
    const int t = base + tid;
    const int ty = t >> 9;
    const int tx = t & (HW - 1);

    #pragma unroll
    for (int j = 0; j < MAXS; j++) s_list[tid][j] = NPIX;   // zero-row padding

    int m1 = 0;            // pass1 fill [0, m1), m1 <= 9
    int p2 = P2OFF;        // pass2 fill [9, p2)

    #pragma unroll
    for (int dy = -1; dy <= 1; dy++) {
        #pragma unroll
        for (int dx = -1; dx <= 1; dx++) {
            const int sy = ty - dy, sx = tx - dx;
            if ((unsigned)sy < HW && (unsigned)sx < HW) {
                const int sidx = sy * HW + sx;

                // pass 1: s -> nnf_sr[s]+d
                const int2 nn = __ldg(&((const int2*)nnf_sr)[sidx]);
                const int qy = nn.x + dy, qx = nn.y + dx;
                if ((unsigned)qy < HW && (unsigned)qx < HW)
                    s_list[tid][m1++] = qy * HW + qx;

                // pass 2: bucket entries r with nnf_rs[r] = s, q = r+d
                int n = g_cnt[sidx];
                if (n > CAP) n = CAP;
                for (int i = 0; i < n; i++) {
                    const int r = g_bucket[i][sidx];          // coalesced (interleaved)
                    const int q2y = (r >> 9) + dy, q2x = (r & (HW - 1)) + dx;
                    if (((unsigned)q2y < HW) & ((unsigned)q2x < HW) && p2 < MAXS)
                        s_list[tid][p2++] = q2y * HW + q2x;
                }
            }
        }
    }
    g_counts[t] = m1 | ((p2 - P2OFF) << 16);
    __syncthreads();

    // coalesced copy-out: 4 warps sweep 128 rows; 20 lanes write int2 each
    const int warp = tid >> 5, lane = tid & 31;
    if (lane < NQ2) {
        for (int r = warp; r < 128; r += 4) {
            int2 v = make_int2(s_list[r][2 * lane], s_list[r][2 * lane + 1]);
            g_list[(size_t)(base + r) * NQ2 + lane] = v;
        }
    }
}

// ---------------------------------------------------------------------------
// 4) Vote: one warp per pixel, FIXED 40-slot branch-free unrolled gather.
//    Padding slots hit the L1-resident zero row (contribute 0).
// ---------------------------------------------------------------------------
__global__ __launch_bounds__(512) void vote_kernel(float* __restrict__ out) {
    __shared__ float s_out[16][65];
    const int warp = threadIdx.x >> 5;            // 0..15 -> pixel within block
    const int lane = threadIdx.x & 31;            // channel pair
    const int pixBase = blockIdx.x * 16;
    const int t = pixBase + warp;

    const int packed = g_counts[t];
    const int m1 = packed & 0xffff;
    const int n2 = packed >> 16;

    int2 myq = make_int2((int)NPIX, (int)NPIX);
    if (lane < NQ2) myq = __ldg(&g_list[(size_t)t * NQ2 + lane]);

    const __half2* __restrict__ refT2 = (const __half2*)g_refT;

    float2 a1 = make_float2(0.f, 0.f);
    float2 a2 = make_float2(0.f, 0.f);

    // Process in chunks of 8: 8 independent loads in flight, no branches.
    #define CHUNK8(J0)                                                          \
    {                                                                           \
        __half2 h[8];                                                           \
        _Pragma("unroll")                                                       \
        for (int k = 0; k < 8; k++) {                                           \
            const int j = (J0) + k;                                             \
            const int q = __shfl_sync(0xffffffffu,                              \
                                      (j & 1) ? myq.y : myq.x, j >> 1);         \
            h[k] = __ldg(&refT2[q * 32 + lane]);                                \
        }                                                                       \
        _Pragma("unroll")                                                       \
        for (int k = 0; k < 8; k++) {                                           \
            const float2 v = __half22float2(h[k]);                              \
            if ((J0) + k < P2OFF) { a1.x += v.x; a1.y += v.y; }                 \
            else                  { a2.x += v.x; a2.y += v.y; }                 \
        }                                                                       \
    }

    CHUNK8(0); CHUNK8(8); CHUNK8(16); CHUNK8(24); CHUNK8(32);
    #undef CHUNK8

    const float ws = 1.0f / (float)NPIX;
    const float wr = 2.0f / (float)NPIX;
    const float w  = ws * (float)m1 + wr * (float)n2;
    const float inv = (w == 0.f) ? 1.f : (1.f / w);
    s_out[warp][2 * lane]     = (ws * a1.x + wr * a2.x) * inv;
    s_out[warp][2 * lane + 1] = (ws * a1.y + wr * a2.y) * inv;
    __syncthreads();

    // Transposed writeout: 512 threads cover 16 pix x 64 ch.
    const int p = threadIdx.x & 15;
    const int c = threadIdx.x >> 4;                   // 0..31
    out[(size_t)c        * NPIX + pixBase + p] = s_out[p][c];
    out[(size_t)(c + 32) * NPIX + pixBase + p] = s_out[p][c + 32];
}

// ---------------------------------------------------------------------------
extern "C" void kernel_launch(void* const* d_in, const int* in_sizes, int n_in,
                              void* d_out, int out_size) {
    const float* ref    = (const float*)d_in[0];
    const int*   nnf_sr = (const int*)d_in[1];
    const int*   nnf_rs = (const int*)d_in[2];
    float*       out    = (float*)d_out;

    dim3 t2d(64, 4);
    transpose_ref_kernel<<<NPIX / 64, t2d>>>(ref);
    zero_cnt_kernel<<<NPIX / 256, 256>>>();
    build_buckets_kernel<<<NPIX / 256, 256>>>(nnf_rs);
    precompute_kernel<<<NPIX / 128, 128>>>(nnf_sr);
    vote_kernel<<<NPIX / 16, 512>>>(out);
}

// round 8
// speedup vs baseline: 1.0808x; 1.0808x over previous
#include <cuda_runtime.h>
#include <cuda_fp16.h>
#include <cstdint>

#define HW    512
#define NPIX  (HW * HW)          // 262144
#define NC    64
#define CAP   16                 // bucket capacity (max Poisson(1) over 262k keys ~ 10)
#define MAXS  44                 // list ints/pixel: pass1 [0,9), pass2 [9, 9+32), pad
#define P2OFF 9
#define N2MAX 32                 // cap on pass2 entries (P(Poisson(9)>32) ~ 1e-10)
#define ZOFF  (NPIX * 128)       // byte offset of the zero row in g_refT

// Scratch (__device__ globals; zero-initialized at load, row NPIX never written)
__device__ __half g_refT[(size_t)(NPIX + 1) * NC];  // +1 zero row for padded slots
__device__ int    g_cnt[NPIX];                      // bucket counts for inverse nnf_rs
__device__ int    g_bucket[CAP][NPIX];              // interleaved: [slot][key] -> ref pixel r
__device__ int4   g_list[(size_t)NPIX * (MAXS/4)];  // pixel-major lists of BYTE offsets
__device__ int    g_counts[NPIX];                   // m1 | (n2 << 16)

// ---------------------------------------------------------------------------
// 1) Transpose + downconvert: ref (C,H,W) fp32 -> refT (H*W, C) fp16.
// ---------------------------------------------------------------------------
__global__ __launch_bounds__(256) void transpose_ref_kernel(const float* __restrict__ ref) {
    __shared__ float tile[64][65];
    const int pixBase = blockIdx.x * 64;
    const int tx = threadIdx.x;   // 0..63
    const int ty = threadIdx.y;   // 0..3

    #pragma unroll
    for (int c = ty; c < NC; c += 4)
        tile[c][tx] = ref[(size_t)c * NPIX + pixBase + tx];   // coalesced over pixels
    __syncthreads();
    #pragma unroll
    for (int p = ty; p < 64; p += 4)
        g_refT[(size_t)(pixBase + p) * NC + tx] = __float2half(tile[tx][p]);
}

// ---------------------------------------------------------------------------
// 2a) Zero bucket counts.  2b) Invert nnf_rs into buckets.
// ---------------------------------------------------------------------------
__global__ __launch_bounds__(256) void zero_cnt_kernel() {
    const int i = blockIdx.x * blockDim.x + threadIdx.x;
    if (i < NPIX) g_cnt[i] = 0;
}
__global__ __launch_bounds__(256) void build_buckets_kernel(const int* __restrict__ nnf_rs) {
    const int r = blockIdx.x * blockDim.x + threadIdx.x;
    if (r >= NPIX) return;
    const int2 nn = ((const int2*)nnf_rs)[r];     // (sy, sx) in [0,512)
    const int key = nn.x * HW + nn.y;
    const int slot = atomicAdd(&g_cnt[key], 1);
    if (slot < CAP) g_bucket[slot][key] = r;
}

// ---------------------------------------------------------------------------
// 3) Precompute lists of PRE-SCALED byte offsets (q * 128). One thread/pixel.
//    Pass1 -> fixed 9 slots (invalid taps -> ZOFF). Pass2 -> [9, 9+n2),
//    remaining slots stay ZOFF (padding reads hit the L1-resident zero row).
// ---------------------------------------------------------------------------
__global__ __launch_bounds__(128) void precompute_kernel(const int* __restrict__ nnf_sr) {
    __shared__ int s_list[128][MAXS + 1];         // +1 pad: conflict-free columns
    const int tid = threadIdx.x;
    const int base = blockIdx.x * 128;
    const int t = base + tid;
    const int ty = t >> 9;
    const int tx = t & (HW - 1);

    #pragma unroll
    for (int j = 0; j < MAXS; j++) s_list[tid][j] = ZOFF;   // zero-row padding

    int m1 = 0;            // pass1 fill [0, m1), m1 <= 9
    int p2 = P2OFF;        // pass2 fill [9, p2)

    #pragma unroll
    for (int dy = -1; dy <= 1; dy++) {
        #pragma unroll
        for (int dx = -1; dx <= 1; dx++) {
            const int sy = ty - dy, sx = tx - dx;
            if ((unsigned)sy < HW && (unsigned)sx < HW) {
                const int sidx = sy * HW + sx;

                // pass 1: s -> nnf_sr[s]+d
                const int2 nn = __ldg(&((const int2*)nnf_sr)[sidx]);
                const int qy = nn.x + dy, qx = nn.y + dx;
                if ((unsigned)qy < HW && (unsigned)qx < HW)
                    s_list[tid][m1++] = (qy * HW + qx) << 7;   // byte offset

                // pass 2: bucket entries r with nnf_rs[r] = s, q = r+d
                int n = g_cnt[sidx];
                if (n > CAP) n = CAP;
                for (int i = 0; i < n; i++) {
                    const int r = g_bucket[i][sidx];          // coalesced (interleaved)
                    const int q2y = (r >> 9) + dy, q2x = (r & (HW - 1)) + dx;
                    if (((unsigned)q2y < HW) & ((unsigned)q2x < HW) &&
                        p2 < P2OFF + N2MAX)
                        s_list[tid][p2++] = ((q2y * HW + q2x) << 7);
                }
            }
        }
    }
    g_counts[t] = m1 | ((p2 - P2OFF) << 16);
    __syncthreads();

    // coalesced copy-out: 4 warps sweep 128 rows; 22 lanes write int2 each
    const int warp = tid >> 5, lane = tid & 31;
    int2* glist2 = (int2*)g_list;
    if (lane < MAXS / 2) {
        for (int r = warp; r < 128; r += 4) {
            int2 v = make_int2(s_list[r][2 * lane], s_list[r][2 * lane + 1]);
            glist2[(size_t)(base + r) * (MAXS / 2) + lane] = v;
        }
    }
}

// ---------------------------------------------------------------------------
// 4) Vote: one warp per pixel. Lists staged in smem (LDS broadcast, no shfl),
//    pass1 = fixed 9-load batch (MLP=9), pass2 = dynamic chunks of 4,
//    packed f32x2 accumulation.
// ---------------------------------------------------------------------------
__global__ __launch_bounds__(512) void vote_kernel(float* __restrict__ out) {
    __shared__ __align__(16) int s_list[16][MAXS];  // 16 pixels x 44 offsets
    __shared__ float s_out[16][65];
    const int tid  = threadIdx.x;
    const int warp = tid >> 5;                    // 0..15 -> pixel within block
    const int lane = tid & 31;                    // channel pair
    const int pixBase = blockIdx.x * 16;

    // Stage 16 lists: 176 int4, coalesced.
    if (tid < 16 * (MAXS / 4))
        ((int4*)s_list)[tid] = __ldg(&g_list[(size_t)pixBase * (MAXS / 4) + tid]);
    __syncthreads();

    const int t = pixBase + warp;
    const int packed = __ldg(&g_counts[t]);
    const int m1 = packed & 0xffff;
    const int n2 = packed >> 16;

    const char* base = (const char*)g_refT + lane * 4;  // this lane's half2 column
    const int* row = s_list[warp];

    unsigned long long a1 = 0ull, a2 = 0ull;      // packed f32x2 accumulators

    #define ACCP(acc, h)                                                      \
    {                                                                         \
        const float2 v_ = __half22float2(h);                                  \
        unsigned long long pv_;                                               \
        asm("mov.b64 %0, {%1, %2};" : "=l"(pv_) : "f"(v_.x), "f"(v_.y));      \
        asm("add.rn.f32x2 %0, %0, %1;" : "+l"(acc) : "l"(pv_));               \
    }

    // --- pass 1: fixed 9 slots, fully batched ---
    {
        __half2 h[9];
        #pragma unroll
        for (int j = 0; j < 9; j++)
            h[j] = __ldg((const __half2*)(base + row[j]));
        #pragma unroll
        for (int j = 0; j < 9; j++)
            ACCP(a1, h[j]);
    }

    // --- pass 2: dynamic, chunks of 4 (padding slots hold ZOFF -> zero row) ---
    {
        const int end = P2OFF + ((n2 + 3) & ~3);
        for (int j = P2OFF; j < end; j += 4) {
            const __half2 h0 = __ldg((const __half2*)(base + row[j]));
            const __half2 h1 = __ldg((const __half2*)(base + row[j + 1]));
            const __half2 h2 = __ldg((const __half2*)(base + row[j + 2]));
            const __half2 h3 = __ldg((const __half2*)(base + row[j + 3]));
            ACCP(a2, h0); ACCP(a2, h1); ACCP(a2, h2); ACCP(a2, h3);
        }
    }
    #undef ACCP

    float2 s1, s2;
    asm("mov.b64 {%0, %1}, %2;" : "=f"(s1.x), "=f"(s1.y) : "l"(a1));
    asm("mov.b64 {%0, %1}, %2;" : "=f"(s2.x), "=f"(s2.y) : "l"(a2));

    const float ws = 1.0f / (float)NPIX;
    const float wr = 2.0f / (float)NPIX;
    const float w  = ws * (float)m1 + wr * (float)n2;
    const float inv = (w == 0.f) ? 1.f : (1.f / w);
    s_out[warp][2 * lane]     = (ws * s1.x + wr * s2.x) * inv;
    s_out[warp][2 * lane + 1] = (ws * s1.y + wr * s2.y) * inv;
    __syncthreads();

    // Transposed writeout: 512 threads cover 16 pix x 64 ch.
    const int p = tid & 15;
    const int c = tid >> 4;                       // 0..31
    out[(size_t)c        * NPIX + pixBase + p] = s_out[p][c];
    out[(size_t)(c + 32) * NPIX + pixBase + p] = s_out[p][c + 32];
}

// ---------------------------------------------------------------------------
extern "C" void kernel_launch(void* const* d_in, const int* in_sizes, int n_in,
                              void* d_out, int out_size) {
    const float* ref    = (const float*)d_in[0];
    const int*   nnf_sr = (const int*)d_in[1];
    const int*   nnf_rs = (const int*)d_in[2];
    float*       out    = (float*)d_out;

    dim3 t2d(64, 4);
    transpose_ref_kernel<<<NPIX / 64, t2d>>>(ref);
    zero_cnt_kernel<<<NPIX / 256, 256>>>();
    build_buckets_kernel<<<NPIX / 256, 256>>>(nnf_rs);
    precompute_kernel<<<NPIX / 128, 128>>>(nnf_sr);
    vote_kernel<<<NPIX / 16, 512>>>(out);
}

// round 9
// speedup vs baseline: 1.4584x; 1.3494x over previous
#include <cuda_runtime.h>
#include <cuda_fp16.h>
#include <cstdint>

#define HW    512
#define NPIX  (HW * HW)          // 262144
#define NC    64
#define CAP   16                 // bucket capacity (max Poisson(1) over 262k keys ~ 10)
#define MAXS  44                 // list ints/pixel: pass1 [0,9), pass2 [9, 9+32), pad
#define P2OFF 9
#define N2MAX 32                 // cap on pass2 entries (P(Poisson(9)>32) ~ 1e-10)
#define ZOFF  (NPIX * 128)       // byte offset of the zero row in g_refT

// Scratch (__device__ globals; zero-initialized at load, row NPIX never written)
__device__ __half g_refT[(size_t)(NPIX + 1) * NC];  // +1 zero row for padded slots
__device__ int    g_cnt[NPIX];                      // bucket counts for inverse nnf_rs
__device__ int    g_bucket[CAP][NPIX];              // interleaved: [slot][key] -> ref pixel r
__device__ int4   g_list[(size_t)NPIX * (MAXS/4)];  // pixel-major lists of BYTE offsets
__device__ int    g_counts[NPIX];                   // m1 | (n2 << 16)

// ---------------------------------------------------------------------------
// 1) Transpose + downconvert: ref (C,H,W) fp32 -> refT (H*W, C) fp16.
//    float4 loads, uint4 (8-half) stores, 128-px tiles. DRAM-BW bound.
// ---------------------------------------------------------------------------
__global__ __launch_bounds__(256) void transpose_ref_kernel(const float* __restrict__ ref) {
    __shared__ float tile[64][129];
    const int pixBase = blockIdx.x * 128;
    const int tid = threadIdx.x;
    const int wc = tid >> 5;      // 0..7
    const int ln = tid & 31;

    #pragma unroll
    for (int it = 0; it < 8; it++) {
        const int c = wc + it * 8;
        const float4 v = __ldg((const float4*)(ref + (size_t)c * NPIX + pixBase + ln * 4));
        tile[c][ln * 4 + 0] = v.x; tile[c][ln * 4 + 1] = v.y;
        tile[c][ln * 4 + 2] = v.z; tile[c][ln * 4 + 3] = v.w;
    }
    __syncthreads();

    #pragma unroll
    for (int it = 0; it < 4; it++) {
        const int idx = tid + it * 256;
        const int px = idx >> 3;          // 0..127
        const int chunk = idx & 7;        // 8 halves per chunk
        const int c0 = chunk * 8;
        uint4 o;
        __half2 h;
        h = __float22half2_rn(make_float2(tile[c0 + 0][px], tile[c0 + 1][px]));
        o.x = *(unsigned*)&h;
        h = __float22half2_rn(make_float2(tile[c0 + 2][px], tile[c0 + 3][px]));
        o.y = *(unsigned*)&h;
        h = __float22half2_rn(make_float2(tile[c0 + 4][px], tile[c0 + 5][px]));
        o.z = *(unsigned*)&h;
        h = __float22half2_rn(make_float2(tile[c0 + 6][px], tile[c0 + 7][px]));
        o.w = *(unsigned*)&h;
        ((uint4*)(g_refT + (size_t)(pixBase + px) * NC))[chunk] = o;
    }
}

// ---------------------------------------------------------------------------
// 2a) Zero bucket counts.  2b) Invert nnf_rs into buckets.
// ---------------------------------------------------------------------------
__global__ __launch_bounds__(256) void zero_cnt_kernel() {
    const int i = blockIdx.x * blockDim.x + threadIdx.x;
    if (i < NPIX) g_cnt[i] = 0;
}
__global__ __launch_bounds__(256) void build_buckets_kernel(const int* __restrict__ nnf_rs) {
    const int r = blockIdx.x * blockDim.x + threadIdx.x;
    if (r >= NPIX) return;
    const int2 nn = ((const int2*)nnf_rs)[r];     // (sy, sx) in [0,512)
    const int key = nn.x * HW + nn.y;
    const int slot = atomicAdd(&g_cnt[key], 1);
    if (slot < CAP) g_bucket[slot][key] = r;
}

// ---------------------------------------------------------------------------
// 3) Precompute lists of PRE-SCALED byte offsets (q * 128). One thread/pixel.
//    Pass1 -> fixed 9 slots (invalid taps -> ZOFF). Pass2 -> [9, 9+n2),
//    remaining slots stay ZOFF (padding reads hit the L1-resident zero row).
// ---------------------------------------------------------------------------
__global__ __launch_bounds__(128) void precompute_kernel(const int* __restrict__ nnf_sr) {
    __shared__ int s_list[128][MAXS + 1];         // +1 pad: conflict-free columns
    const int tid = threadIdx.x;
    const int base = blockIdx.x * 128;
    const int t = base + tid;
    const int ty = t >> 9;
    const int tx = t & (HW - 1);

    #pragma unroll
    for (int j = 0; j < MAXS; j++) s_list[tid][j] = ZOFF;   // zero-row padding

    int m1 = 0;            // pass1 fill [0, m1), m1 <= 9
    int p2 = P2OFF;        // pass2 fill [9, p2)

    #pragma unroll
    for (int dy = -1; dy <= 1; dy++) {
        #pragma unroll
        for (int dx = -1; dx <= 1; dx++) {
            const int sy = ty - dy, sx = tx - dx;
            if ((unsigned)sy < HW && (unsigned)sx < HW) {
                const int sidx = sy * HW + sx;

                // pass 1: s -> nnf_sr[s]+d
                const int2 nn = __ldg(&((const int2*)nnf_sr)[sidx]);
                const int qy = nn.x + dy, qx = nn.y + dx;
                if ((unsigned)qy < HW && (unsigned)qx < HW)
                    s_list[tid][m1++] = (qy * HW + qx) << 7;   // byte offset

                // pass 2: bucket entries r with nnf_rs[r] = s, q = r+d
                int n = g_cnt[sidx];
                if (n > CAP) n = CAP;
                for (int i = 0; i < n; i++) {
                    const int r = g_bucket[i][sidx];          // coalesced (interleaved)
                    const int q2y = (r >> 9) + dy, q2x = (r & (HW - 1)) + dx;
                    if (((unsigned)q2y < HW) & ((unsigned)q2x < HW) &&
                        p2 < P2OFF + N2MAX)
                        s_list[tid][p2++] = ((q2y * HW + q2x) << 7);
                }
            }
        }
    }
    g_counts[t] = m1 | ((p2 - P2OFF) << 16);
    __syncthreads();

    // coalesced copy-out: 4 warps sweep 128 rows; 22 lanes write int2 each
    const int warp = tid >> 5, lane = tid & 31;
    int2* glist2 = (int2*)g_list;
    if (lane < MAXS / 2) {
        for (int r = warp; r < 128; r += 4) {
            int2 v = make_int2(s_list[r][2 * lane], s_list[r][2 * lane + 1]);
            glist2[(size_t)(base + r) * (MAXS / 2) + lane] = v;
        }
    }
}

// ---------------------------------------------------------------------------
// 4) Vote: FOUR pixels per warp. Lane l serves pixel-group l>>3 with a 16-byte
//    LDG.128 (8 channels) -> one warp load touches 4 random rows (512 B).
//    Lists smem-staged (4 distinct banks per LDS), f32x2 packed accumulation.
// ---------------------------------------------------------------------------
__global__ __launch_bounds__(512) void vote_kernel(float* __restrict__ out) {
    __shared__ __align__(16) int s_list[64][MAXS];   // 64 pixels x 44 offsets
    __shared__ float s_out[64][65];
    const int tid  = threadIdx.x;
    const int warp = tid >> 5;                    // 0..15
    const int lane = tid & 31;
    const int pixBase = blockIdx.x * 64;

    // Stage 64 lists: 64 * 11 = 704 int4, coalesced.
    #pragma unroll
    for (int i = tid; i < 64 * (MAXS / 4); i += 512)
        ((int4*)s_list)[i] = __ldg(&g_list[(size_t)pixBase * (MAXS / 4) + i]);
    __syncthreads();

    const int group = lane >> 3;                  // 0..3 -> pixel within warp
    const int sub   = lane & 7;                   // 16-byte chunk within row
    const int px    = warp * 4 + group;           // 0..63
    const int t     = pixBase + px;

    const int packed = __ldg(&g_counts[t]);
    const int m1 = packed & 0xffff;
    const int n2 = packed >> 16;
    // warp max of n2 across the 4 groups
    int n2max = n2;
    n2max = max(n2max, __shfl_xor_sync(0xffffffffu, n2max, 8));
    n2max = max(n2max, __shfl_xor_sync(0xffffffffu, n2max, 16));

    const char* base = (const char*)g_refT + sub * 16;
    const int* row = s_list[px];

    unsigned long long a1[4] = {0ull, 0ull, 0ull, 0ull};
    unsigned long long a2[4] = {0ull, 0ull, 0ull, 0ull};

    #define ACC1(acc, u)                                                      \
    {                                                                         \
        const float2 v_ = __half22float2(*(const __half2*)&(u));              \
        unsigned long long pv_;                                               \
        asm("mov.b64 %0, {%1, %2};" : "=l"(pv_) : "f"(v_.x), "f"(v_.y));      \
        asm("add.rn.f32x2 %0, %0, %1;" : "+l"(acc) : "l"(pv_));               \
    }
    #define ACC8(acc, d) { ACC1(acc[0], (d).x); ACC1(acc[1], (d).y);          \
                           ACC1(acc[2], (d).z); ACC1(acc[3], (d).w); }

    // --- pass 1: fixed 9 slots, chunks of 3 (12 lines in flight) ---
    #pragma unroll
    for (int jb = 0; jb < 9; jb += 3) {
        const uint4 d0 = __ldg((const uint4*)(base + row[jb]));
        const uint4 d1 = __ldg((const uint4*)(base + row[jb + 1]));
        const uint4 d2 = __ldg((const uint4*)(base + row[jb + 2]));
        ACC8(a1, d0); ACC8(a1, d1); ACC8(a1, d2);
    }

    // --- pass 2: dynamic to warp-max, chunks of 2 (8 lines in flight) ---
    {
        const int end = P2OFF + ((n2max + 1) & ~1);
        for (int j = P2OFF; j < end; j += 2) {
            const uint4 d0 = __ldg((const uint4*)(base + row[j]));
            const uint4 d1 = __ldg((const uint4*)(base + row[j + 1]));
            ACC8(a2, d0); ACC8(a2, d1);
        }
    }
    #undef ACC8
    #undef ACC1

    const float ws = 1.0f / (float)NPIX;
    const float wr = 2.0f / (float)NPIX;
    const float w  = ws * (float)m1 + wr * (float)n2;
    const float inv = (w == 0.f) ? 1.f : (1.f / w);

    #pragma unroll
    for (int k = 0; k < 4; k++) {
        float2 v1, v2;
        asm("mov.b64 {%0, %1}, %2;" : "=f"(v1.x), "=f"(v1.y) : "l"(a1[k]));
        asm("mov.b64 {%0, %1}, %2;" : "=f"(v2.x), "=f"(v2.y) : "l"(a2[k]));
        s_out[px][sub * 8 + 2 * k]     = (ws * v1.x + wr * v2.x) * inv;
        s_out[px][sub * 8 + 2 * k + 1] = (ws * v1.y + wr * v2.y) * inv;
    }
    __syncthreads();

    // Writeout: 64 px x 64 ch = 4096 floats, coalesced 64-float rows.
    #pragma unroll
    for (int i = tid; i < 4096; i += 512) {
        const int c = i >> 6;
        const int p = i & 63;
        out[(size_t)c * NPIX + pixBase + p] = s_out[p][c];
    }
}

// ---------------------------------------------------------------------------
extern "C" void kernel_launch(void* const* d_in, const int* in_sizes, int n_in,
                              void* d_out, int out_size) {
    const float* ref    = (const float*)d_in[0];
    const int*   nnf_sr = (const int*)d_in[1];
    const int*   nnf_rs = (const int*)d_in[2];
    float*       out    = (float*)d_out;

    transpose_ref_kernel<<<NPIX / 128, 256>>>(ref);
    zero_cnt_kernel<<<NPIX / 256, 256>>>();
    build_buckets_kernel<<<NPIX / 256, 256>>>(nnf_rs);
    precompute_kernel<<<NPIX / 128, 128>>>(nnf_sr);
    vote_kernel<<<NPIX / 64, 512>>>(out);
}